// round 15
// baseline (speedup 1.0000x reference)
#include <cuda_runtime.h>
#include <cuda_bf16.h>

#define BB 16384
#define SS 4
#define LL 16
#define DD 256
#define BOS_ID 98
#define N_CHAR 58
#define D4 (DD / 4)              // 64 float4 per row
#define OUTROWS (BB * 5)         // 81920

#define THREADS 512
#define BLOCKS  296              // 2 per SM
#define WTOT    (BLOCKS * (THREADS / 32))   // 4736 warps
#define SROWS   48               // table rows resident in smem (48KB)

typedef unsigned long long u64;

__device__ __forceinline__ void add2(u64& a, u64 e) {
    asm("add.rn.f32x2 %0, %0, %1;" : "+l"(a) : "l"(e));
}
__device__ __forceinline__ void fma2(u64& a, u64 m, u64 e) {
    asm("fma.rn.f32x2 %0, %1, %2, %0;" : "+l"(a) : "l"(m), "l"(e));
}
__device__ __forceinline__ u64 dup2(float m) {
    u64 r; asm("mov.b64 %0, {%1, %1};" : "=l"(r) : "f"(m)); return r;
}
__device__ __forceinline__ void mul2(u64& a, u64 m) {
    asm("mul.rn.f32x2 %0, %0, %1;" : "+l"(a) : "l"(m));
}
// Streaming store: evict-first in L2 so dirty output lines drain promptly.
__device__ __forceinline__ void stcs16(ulonglong2* p, ulonglong2 v) {
    asm volatile("st.global.cs.v2.u64 [%0], {%1, %2};"
                 :: "l"(p), "l"(v.x), "l"(v.y) : "memory");
}
// evict_last cache policy (inputs pinned in L2 across graph replays).
__device__ __forceinline__ u64 mk_policy() {
    u64 pol;
    asm volatile("createpolicy.fractional.L2::evict_last.b64 %0, 1.0;" : "=l"(pol));
    return pol;
}
__device__ __forceinline__ int ldg_el_i(const int* p, u64 pol) {
    int v;
    asm volatile("ld.global.nc.L2::cache_hint.b32 %0, [%1], %2;"
                 : "=r"(v) : "l"(p), "l"(pol));
    return v;
}
__device__ __forceinline__ int4 ldg_el_i4(const int4* p, u64 pol) {
    int4 v;
    asm volatile("ld.global.nc.L2::cache_hint.v4.b32 {%0,%1,%2,%3}, [%4], %5;"
                 : "=r"(v.x), "=r"(v.y), "=r"(v.z), "=r"(v.w) : "l"(p), "l"(pol));
    return v;
}
__device__ __forceinline__ ulonglong2 ldg_el_u2(const void* p, u64 pol) {
    ulonglong2 v;
    asm volatile("ld.global.nc.L2::cache_hint.v2.u64 {%0,%1}, [%2], %3;"
                 : "=l"(v.x), "=l"(v.y) : "l"(p), "l"(pol));
    return v;
}

__global__ void __launch_bounds__(THREADS, 2) actions_emb_kernel(
    const int*    __restrict__ char_ids,     // (B, S, L)
    const int*    __restrict__ char_len,     // (B, S)
    const int*    __restrict__ action_ids,   // (B, S)
    const int*    __restrict__ slot_type,    // (B, S)
    const float4* __restrict__ char_table,   // (N_CHAR, 64)
    const float4* __restrict__ action_table, // (N_ACT, 64)
    ulonglong2*   __restrict__ out)          // (B, 5, 64)
{
    __shared__ float4 s_tab[SROWS * D4];     // 48 KB

    const u64 pol = mk_policy();

    for (int i = threadIdx.x; i < SROWS * D4; i += THREADS) {
        const ulonglong2 t = ldg_el_u2(&char_table[i], pol);
        *(ulonglong2*)&s_tab[i] = t;
    }
    __syncthreads();

    const int warp = threadIdx.x >> 5;
    const int lane = threadIdx.x & 31;
    const ulonglong2* at = (const ulonglong2*)action_table;

    for (int row = blockIdx.x * (THREADS / 32) + warp; row < OUTROWS; row += WTOT) {
        const int b = row / 5;
        const int s = row - b * 5;
        ulonglong2 r0, r1;

        if (s == 0) {
            r0 = ldg_el_u2(&at[BOS_ID * D4 + lane], pol);
            r1 = ldg_el_u2(&at[BOS_ID * D4 + 32 + lane], pol);
        } else {
            const int bs = b * SS + s - 1;
            // 7 independent control loads -> one DRAM round-trip (L2-pinned).
            const int  st  = ldg_el_i(&slot_type[bs], pol);
            const int  len = ldg_el_i(&char_len[bs], pol);   // 1..15
            const int  ai  = ldg_el_i(&action_ids[bs], pol);
            const int4* p  = (const int4*)(char_ids + bs * LL);
            const int4 i0  = ldg_el_i4(&p[0], pol);
            const int4 i1  = ldg_el_i4(&p[1], pol);
            const int4 i2  = ldg_el_i4(&p[2], pol);
            const int4 i3  = ldg_el_i4(&p[3], pol);

            if (st == 0) {
                u64 a0l = 0, a0h = 0, a1l = 0, a1h = 0;
                #define GPAIR(ia, ib, base)                                        \
                if (len > (base)) {                                                \
                    const ulonglong2 ea0 = ((ia) < SROWS)                          \
                        ? *(const ulonglong2*)&s_tab[(ia) * D4 + lane]             \
                        : ldg_el_u2(&char_table[(ia) * D4 + lane], pol);           \
                    const ulonglong2 ea1 = ((ia) < SROWS)                          \
                        ? *(const ulonglong2*)&s_tab[(ia) * D4 + 32 + lane]        \
                        : ldg_el_u2(&char_table[(ia) * D4 + 32 + lane], pol);      \
                    const ulonglong2 eb0 = ((ib) < SROWS)                          \
                        ? *(const ulonglong2*)&s_tab[(ib) * D4 + lane]             \
                        : ldg_el_u2(&char_table[(ib) * D4 + lane], pol);           \
                    const ulonglong2 eb1 = ((ib) < SROWS)                          \
                        ? *(const ulonglong2*)&s_tab[(ib) * D4 + 32 + lane]        \
                        : ldg_el_u2(&char_table[(ib) * D4 + 32 + lane], pol);      \
                    add2(a0l, ea0.x); add2(a0h, ea0.y);                            \
                    add2(a1l, ea1.x); add2(a1h, ea1.y);                            \
                    const u64 m = dup2(((base) + 1 < len) ? 1.0f : 0.0f);          \
                    fma2(a0l, m, eb0.x); fma2(a0h, m, eb0.y);                      \
                    fma2(a1l, m, eb1.x); fma2(a1h, m, eb1.y);                      \
                }
                GPAIR(i0.x, i0.y,  0)
                GPAIR(i0.z, i0.w,  2)
                GPAIR(i1.x, i1.y,  4)
                GPAIR(i1.z, i1.w,  6)
                GPAIR(i2.x, i2.y,  8)
                GPAIR(i2.z, i2.w, 10)
                GPAIR(i3.x, i3.y, 12)
                GPAIR(i3.z, i3.w, 14)
                #undef GPAIR
                const u64 inv = dup2(1.0f / (float)len);
                mul2(a0l, inv); mul2(a0h, inv); mul2(a1l, inv); mul2(a1h, inv);
                r0.x = a0l; r0.y = a0h;
                r1.x = a1l; r1.y = a1h;
            } else if (st == 1) {
                r0 = ldg_el_u2(&at[ai * D4 + lane], pol);
                r1 = ldg_el_u2(&at[ai * D4 + 32 + lane], pol);
            } else {
                r0.x = 0; r0.y = 0;
                r1.x = 0; r1.y = 0;
            }
        }

        ulonglong2* o = out + (long long)row * D4;
        stcs16(o + lane,      r0);
        stcs16(o + lane + 32, r1);
    }
}

extern "C" void kernel_launch(void* const* d_in, const int* in_sizes, int n_in,
                              void* d_out, int out_size)
{
    const int*    char_ids     = (const int*)   d_in[0];
    const int*    char_len     = (const int*)   d_in[1];
    const int*    action_ids   = (const int*)   d_in[2];
    const int*    slot_type    = (const int*)   d_in[3];
    const float4* char_table   = (const float4*)d_in[4];
    const float4* action_table = (const float4*)d_in[5];
    ulonglong2*   out          = (ulonglong2*)  d_out;

    actions_emb_kernel<<<BLOCKS, THREADS>>>(char_ids, char_len, action_ids,
                                            slot_type, char_table, action_table, out);
}